// round 1
// baseline (speedup 1.0000x reference)
#include <cuda_runtime.h>
#include <math.h>

#define BB 64
#define TT 512
#define HH 1024
#define BT (BB*TT)
#define NF 256
#define NCHUNK 64
#define ROWS_PER_CHUNK (BT/NCHUNK)  // 512

// ---------------- device scratch (no allocations allowed) ----------------
__device__ float g_part_sum[NCHUNK][HH];
__device__ float g_part_sq[NCHUNK][HH];
__device__ float g_a[HH];        // per-channel coefficient gamma*rstd*Wp
__device__ float g_C;            // constant term incl. bp
__device__ float g_WpL1;         // sum|Wp| + |bp|  (rigorous |f| bound)
__device__ float g_px[BT];
__device__ float g_blockmax[BT/8];
__device__ float g_s0, g_delta, g_invd;
__device__ float g_phi[NF][HH];
__device__ float g_gi[NF][3*HH];
__device__ float g_Ftab[NF];

// ---------------- pass 1: per-channel BN partial sums ----------------
__global__ void k_stats(const float* __restrict__ x) {
    int ch = blockIdx.x * 256 + threadIdx.x;
    int r0 = blockIdx.y * ROWS_PER_CHUNK;
    const float* p = x + (size_t)r0 * HH + ch;
    float s = 0.f, q = 0.f;
    for (int r = 0; r < ROWS_PER_CHUNK; r++) {
        float v = p[(size_t)r * HH];
        s += v; q += v * v;
    }
    g_part_sum[blockIdx.y][ch] = s;
    g_part_sq[blockIdx.y][ch]  = q;
}

// finalize stats -> a[j], C, WpL1
__global__ void k_finalize(const float* __restrict__ gamma, const float* __restrict__ beta,
                           const float* __restrict__ Wp, const float* __restrict__ bp) {
    int j = threadIdx.x;  // 1024 threads
    float s = 0.f, q = 0.f;
    for (int c = 0; c < NCHUNK; c++) { s += g_part_sum[c][j]; q += g_part_sq[c][j]; }
    float mean = s * (1.0f / BT);
    float var  = q * (1.0f / BT) - mean * mean;
    float rstd = rsqrtf(var + 1e-5f);
    float gj = gamma[j], wj = Wp[j];
    g_a[j] = gj * rstd * wj;
    float cj = (beta[j] - mean * rstd * gj) * wj;
    float aw = fabsf(wj);
    __shared__ float sc[1024], sa[1024];
    sc[j] = cj; sa[j] = aw;
    __syncthreads();
    for (int st = 512; st > 0; st >>= 1) {
        if (j < st) { sc[j] += sc[j + st]; sa[j] += sa[j + st]; }
        __syncthreads();
    }
    if (j == 0) { g_C = sc[0] + bp[0]; g_WpL1 = sa[0] + fabsf(bp[0]); }
}

// ---------------- pass 2: px[b,t] = dot(x_row, a) + C, plus block max|px| ----------------
__global__ void k_px(const float* __restrict__ x) {
    int w = threadIdx.x >> 5, lane = threadIdx.x & 31;
    int r = blockIdx.x * 8 + w;
    const float4* xr = (const float4*)(x + (size_t)r * HH);
    const float4* a4 = (const float4*)g_a;
    float acc = 0.f;
#pragma unroll
    for (int i = 0; i < 8; i++) {
        float4 xv = xr[lane + i * 32];
        float4 av = __ldg(&a4[lane + i * 32]);
        acc += xv.x * av.x + xv.y * av.y + xv.z * av.z + xv.w * av.w;
    }
#pragma unroll
    for (int off = 16; off; off >>= 1) acc += __shfl_down_sync(0xFFFFFFFFu, acc, off);
    __shared__ float wm[8];
    if (lane == 0) { float v = acc + g_C; g_px[r] = v; wm[w] = fabsf(v); }
    __syncthreads();
    if (threadIdx.x == 0) {
        float m = wm[0];
#pragma unroll
        for (int i = 1; i < 8; i++) m = fmaxf(m, wm[i]);
        g_blockmax[blockIdx.x] = m;
    }
}

// deterministic max reduce -> table domain
__global__ void k_domain() {
    __shared__ float sm[1024];
    int t = threadIdx.x;
    float m = 0.f;
    for (int i = t; i < BT / 8; i += 1024) m = fmaxf(m, g_blockmax[i]);
    sm[t] = m; __syncthreads();
    for (int st = 512; st > 0; st >>= 1) {
        if (t < st) sm[t] = fmaxf(sm[t], sm[t + st]);
        __syncthreads();
    }
    if (t == 0) {
        // |s| <= (max|px| + max|f|)/2, with |f| <= WpL1 rigorously
        float R = 0.5f * (sm[0] + g_WpL1) * 1.02f + 0.25f;
        g_s0 = -R;
        g_delta = 2.f * R / (float)(NF - 1);
        g_invd = (float)(NF - 1) / (2.f * R);
    }
}

// ---------------- table build: layer-0 GRU-cell(h=0) at sample points ----------------
__global__ void k_phi(const float* __restrict__ W0, const float* __restrict__ bih0,
                      const float* __restrict__ bhh0) {
    int i = blockIdx.x;
    int j = blockIdx.y * 256 + threadIdx.x;
    float s = g_s0 + (float)i * g_delta;
    float ar = fmaf(s, W0[j],          bih0[j]        + bhh0[j]);
    float az = fmaf(s, W0[HH + j],     bih0[HH + j]   + bhh0[HH + j]);
    float r = 1.f / (1.f + expf(-ar));
    float z = 1.f / (1.f + expf(-az));
    float an = fmaf(s, W0[2 * HH + j], fmaf(r, bhh0[2 * HH + j], bih0[2 * HH + j]));
    float n = tanhf(an);
    g_phi[i][j] = (1.f - z) * n;
}

// gi[i][k] = sum_j phi[i][j]*W1[k][j] + bih1[k]   (M=NF, N=3072, K=1024)
__global__ void k_gemm(const float* __restrict__ W1, const float* __restrict__ bih1) {
    __shared__ float As[16][68];
    __shared__ float Bs[16][68];
    int tid = threadIdx.x;                 // 256
    int m0 = blockIdx.y * 64, n0 = blockIdx.x * 64;
    int lrow = tid >> 2, lk4 = (tid & 3) * 4;
    int mt = (tid >> 4) * 4, nt = (tid & 15) * 4;
    float acc[4][4] = {};
    for (int k0 = 0; k0 < HH; k0 += 16) {
        float4 av = *(const float4*)&g_phi[m0 + lrow][k0 + lk4];
        float4 bv = *(const float4*)&W1[(size_t)(n0 + lrow) * HH + k0 + lk4];
        As[lk4 + 0][lrow] = av.x; As[lk4 + 1][lrow] = av.y;
        As[lk4 + 2][lrow] = av.z; As[lk4 + 3][lrow] = av.w;
        Bs[lk4 + 0][lrow] = bv.x; Bs[lk4 + 1][lrow] = bv.y;
        Bs[lk4 + 2][lrow] = bv.z; Bs[lk4 + 3][lrow] = bv.w;
        __syncthreads();
#pragma unroll
        for (int kk = 0; kk < 16; kk++) {
            float4 a4v = *(const float4*)&As[kk][mt];
            float4 b4v = *(const float4*)&Bs[kk][nt];
            float a_[4] = {a4v.x, a4v.y, a4v.z, a4v.w};
            float b_[4] = {b4v.x, b4v.y, b4v.z, b4v.w};
#pragma unroll
            for (int r = 0; r < 4; r++)
#pragma unroll
                for (int c = 0; c < 4; c++)
                    acc[r][c] = fmaf(a_[r], b_[c], acc[r][c]);
        }
        __syncthreads();
    }
    float bias[4];
#pragma unroll
    for (int c = 0; c < 4; c++) bias[c] = bih1[n0 + nt + c];
#pragma unroll
    for (int r = 0; r < 4; r++) {
        float4 o;
        o.x = acc[r][0] + bias[0];
        o.y = acc[r][1] + bias[1];
        o.z = acc[r][2] + bias[2];
        o.w = acc[r][3] + bias[3];
        *(float4*)&g_gi[m0 + mt + r][n0 + nt] = o;
    }
}

// layer-1 nonlinearity + projection dot -> F table
__global__ void k_tail(const float* __restrict__ bhh1, const float* __restrict__ Wp,
                       const float* __restrict__ bp) {
    int i = blockIdx.x;
    float acc = 0.f;
    for (int ch = threadIdx.x; ch < HH; ch += 256) {
        float r = 1.f / (1.f + expf(-(g_gi[i][ch] + bhh1[ch])));
        float z = 1.f / (1.f + expf(-(g_gi[i][HH + ch] + bhh1[HH + ch])));
        float n = tanhf(g_gi[i][2 * HH + ch] + r * bhh1[2 * HH + ch]);
        acc += Wp[ch] * (1.f - z) * n;
    }
    __shared__ float sm[256];
    sm[threadIdx.x] = acc; __syncthreads();
    for (int st = 128; st > 0; st >>= 1) {
        if (threadIdx.x < st) sm[threadIdx.x] += sm[threadIdx.x + st];
        __syncthreads();
    }
    if (threadIdx.x == 0) g_Ftab[i] = sm[0] + bp[0];
}

// ---------------- sequential scan: 64 independent scalar recurrences ----------------
__global__ void k_scan(float* __restrict__ out) {
    __shared__ float tab[NF];
    int tid = threadIdx.x;  // 64
    for (int i = tid; i < NF; i += 64) tab[i] = g_Ftab[i];
    __syncthreads();
    float s0 = g_s0, invd = g_invd;
    const float* px = g_px + tid * TT;
    float* o = out + tid * TT;
    float f = 0.f;
    for (int t = 0; t < TT; t++) {
        float s = 0.5f * (f + px[t]);
        float u = (s - s0) * invd;
        u = fminf(fmaxf(u, 1.0f), (float)(NF - 2) - 1e-3f);
        float fi = floorf(u);
        int i = (int)fi;
        float xx = u - fi;
        float p0 = tab[i - 1], p1 = tab[i], p2 = tab[i + 1], p3 = tab[i + 2];
        // 4-point Lagrange cubic on uniform grid (exact for cubics, O(d^4) error)
        float xm1 = xx - 1.f, xm2 = xx - 2.f, xp1 = xx + 1.f;
        float w0 = -xx * xm1 * xm2 * (1.f / 6.f);
        float w1 =  xp1 * xm1 * xm2 * 0.5f;
        float w2 = -xp1 * xx  * xm2 * 0.5f;
        float w3 =  xp1 * xx  * xm1 * (1.f / 6.f);
        f = fmaf(w0, p0, fmaf(w1, p1, fmaf(w2, p2, w3 * p3)));
        o[t] = f;
    }
}

extern "C" void kernel_launch(void* const* d_in, const int* in_sizes, int n_in,
                              void* d_out, int out_size) {
    const float* x     = (const float*)d_in[0];
    // d_in[1] timestamp: unused (only its length T matters, fixed = 512)
    const float* gamma = (const float*)d_in[2];
    const float* beta  = (const float*)d_in[3];
    const float* Wih0  = (const float*)d_in[4];
    const float* bih0  = (const float*)d_in[5];
    // d_in[6] W_hh0 unused (h_prev = 0)
    const float* bhh0  = (const float*)d_in[7];
    const float* Wih1  = (const float*)d_in[8];
    const float* bih1  = (const float*)d_in[9];
    // d_in[10] W_hh1 unused
    const float* bhh1  = (const float*)d_in[11];
    const float* Wp    = (const float*)d_in[12];
    const float* bp    = (const float*)d_in[13];
    float* out = (float*)d_out;

    k_stats<<<dim3(4, 64), 256>>>(x);
    k_finalize<<<1, 1024>>>(gamma, beta, Wp, bp);
    k_px<<<BT / 8, 256>>>(x);
    k_domain<<<1, 1024>>>();
    k_phi<<<dim3(NF, 4), 256>>>(Wih0, bih0, bhh0);
    k_gemm<<<dim3(48, NF / 64), 256>>>(Wih1, bih1);
    k_tail<<<NF, 256>>>(bhh1, Wp, bp);
    k_scan<<<1, 64>>>(out);
}

// round 2
// speedup vs baseline: 1.1906x; 1.1906x over previous
#include <cuda_runtime.h>
#include <math.h>

#define BB 64
#define TT 512
#define HH 1024
#define BT (BB*TT)
#define NF 128
#define NCHUNK 64
#define ROWS_PER_CHUNK (BT/NCHUNK)  // 512

// ---------------- device scratch (no allocations allowed) ----------------
__device__ float g_part_sum[NCHUNK][HH];
__device__ float g_part_sq[NCHUNK][HH];
__device__ float g_a[HH];          // per-channel coefficient gamma*rstd*Wp
__device__ float g_C;              // constant term incl. bp
__device__ float g_WpL1;           // sum|Wp| + |bp|  (rigorous |f| bound)
__device__ unsigned g_pxmax_u;     // bits of max|px| (positive floats order as uints)
__device__ float g_pxT[TT][BB];    // px transposed: [t][b] for coalesced scan loads
__device__ float g_phi[NF][HH];
__device__ float g_gi[NF][3*HH];
__device__ float g_Ftab[NF];

// domain params computed identically (bit-exact) wherever needed
__device__ __forceinline__ float domain_R() {
    float pxmax = __uint_as_float(g_pxmax_u);
    return 0.5f * (pxmax + g_WpL1) * 1.02f + 0.25f;
}

// ---------------- pass 1: per-channel BN partial sums ----------------
__global__ void k_stats(const float* __restrict__ x) {
    int ch = blockIdx.x * 256 + threadIdx.x;
    int r0 = blockIdx.y * ROWS_PER_CHUNK;
    const float* p = x + (size_t)r0 * HH + ch;
    float s = 0.f, q = 0.f;
#pragma unroll 8
    for (int r = 0; r < ROWS_PER_CHUNK; r++) {
        float v = p[(size_t)r * HH];
        s += v; q += v * v;
    }
    g_part_sum[blockIdx.y][ch] = s;
    g_part_sq[blockIdx.y][ch]  = q;
}

// finalize stats -> a[j], C, WpL1; also resets the px-max atomic for this replay
__global__ void k_finalize(const float* __restrict__ gamma, const float* __restrict__ beta,
                           const float* __restrict__ Wp, const float* __restrict__ bp) {
    int j = threadIdx.x;  // 1024 threads
    float s = 0.f, q = 0.f;
#pragma unroll 8
    for (int c = 0; c < NCHUNK; c++) { s += g_part_sum[c][j]; q += g_part_sq[c][j]; }
    float mean = s * (1.0f / BT);
    float var  = q * (1.0f / BT) - mean * mean;
    float rstd = rsqrtf(var + 1e-5f);
    float gj = gamma[j], wj = Wp[j];
    g_a[j] = gj * rstd * wj;
    float cj = (beta[j] - mean * rstd * gj) * wj;
    float aw = fabsf(wj);
    __shared__ float sc[1024], sa[1024];
    sc[j] = cj; sa[j] = aw;
    __syncthreads();
    for (int st = 512; st > 0; st >>= 1) {
        if (j < st) { sc[j] += sc[j + st]; sa[j] += sa[j + st]; }
        __syncthreads();
    }
    if (j == 0) {
        g_C = sc[0] + bp[0];
        g_WpL1 = sa[0] + fabsf(bp[0]);
        g_pxmax_u = 0u;  // reset deterministic max for this graph replay
    }
}

// ---------------- pass 2: px[b,t] -> transposed store + global max|px| ----------------
__global__ void k_px(const float* __restrict__ x) {
    int w = threadIdx.x >> 5, lane = threadIdx.x & 31;
    int r = blockIdx.x * 8 + w;
    const float4* xr = (const float4*)(x + (size_t)r * HH);
    const float4* a4 = (const float4*)g_a;
    float acc = 0.f;
#pragma unroll
    for (int i = 0; i < 8; i++) {
        float4 xv = xr[lane + i * 32];
        float4 av = __ldg(&a4[lane + i * 32]);
        acc += xv.x * av.x + xv.y * av.y + xv.z * av.z + xv.w * av.w;
    }
#pragma unroll
    for (int off = 16; off; off >>= 1) acc += __shfl_down_sync(0xFFFFFFFFu, acc, off);
    __shared__ float wm[8];
    if (lane == 0) {
        float v = acc + g_C;
        int b = r >> 9, t = r & (TT - 1);
        g_pxT[t][b] = v;
        wm[w] = fabsf(v);
    }
    __syncthreads();
    if (threadIdx.x == 0) {
        float m = wm[0];
#pragma unroll
        for (int i = 1; i < 8; i++) m = fmaxf(m, wm[i]);
        atomicMax(&g_pxmax_u, __float_as_uint(m));  // m >= 0: uint order == float order
    }
}

// ---------------- table build: layer-0 GRU-cell(h=0) at sample points ----------------
__global__ void k_phi(const float* __restrict__ W0, const float* __restrict__ bih0,
                      const float* __restrict__ bhh0) {
    float R = domain_R();
    float s0 = -R;
    float delta = 2.f * R / (float)(NF - 1);
    int i = blockIdx.x;
    int j = blockIdx.y * 256 + threadIdx.x;
    float s = s0 + (float)i * delta;
    float ar = fmaf(s, W0[j],          bih0[j]        + bhh0[j]);
    float az = fmaf(s, W0[HH + j],     bih0[HH + j]   + bhh0[HH + j]);
    float r = 1.f / (1.f + expf(-ar));
    float z = 1.f / (1.f + expf(-az));
    float an = fmaf(s, W0[2 * HH + j], fmaf(r, bhh0[2 * HH + j], bih0[2 * HH + j]));
    float n = tanhf(an);
    g_phi[i][j] = (1.f - z) * n;
}

// gi[i][k] = sum_j phi[i][j]*W1[k][j] + bih1[k]   (M=NF, N=3072, K=1024)
__global__ void k_gemm(const float* __restrict__ W1, const float* __restrict__ bih1) {
    __shared__ float As[16][68];
    __shared__ float Bs[16][68];
    int tid = threadIdx.x;                 // 256
    int m0 = blockIdx.y * 64, n0 = blockIdx.x * 64;
    int lrow = tid >> 2, lk4 = (tid & 3) * 4;
    int mt = (tid >> 4) * 4, nt = (tid & 15) * 4;
    float acc[4][4] = {};
    for (int k0 = 0; k0 < HH; k0 += 16) {
        float4 av = *(const float4*)&g_phi[m0 + lrow][k0 + lk4];
        float4 bv = *(const float4*)&W1[(size_t)(n0 + lrow) * HH + k0 + lk4];
        As[lk4 + 0][lrow] = av.x; As[lk4 + 1][lrow] = av.y;
        As[lk4 + 2][lrow] = av.z; As[lk4 + 3][lrow] = av.w;
        Bs[lk4 + 0][lrow] = bv.x; Bs[lk4 + 1][lrow] = bv.y;
        Bs[lk4 + 2][lrow] = bv.z; Bs[lk4 + 3][lrow] = bv.w;
        __syncthreads();
#pragma unroll
        for (int kk = 0; kk < 16; kk++) {
            float4 a4v = *(const float4*)&As[kk][mt];
            float4 b4v = *(const float4*)&Bs[kk][nt];
            float a_[4] = {a4v.x, a4v.y, a4v.z, a4v.w};
            float b_[4] = {b4v.x, b4v.y, b4v.z, b4v.w};
#pragma unroll
            for (int r = 0; r < 4; r++)
#pragma unroll
                for (int c = 0; c < 4; c++)
                    acc[r][c] = fmaf(a_[r], b_[c], acc[r][c]);
        }
        __syncthreads();
    }
    float bias[4];
#pragma unroll
    for (int c = 0; c < 4; c++) bias[c] = bih1[n0 + nt + c];
#pragma unroll
    for (int r = 0; r < 4; r++) {
        float4 o;
        o.x = acc[r][0] + bias[0];
        o.y = acc[r][1] + bias[1];
        o.z = acc[r][2] + bias[2];
        o.w = acc[r][3] + bias[3];
        *(float4*)&g_gi[m0 + mt + r][n0 + nt] = o;
    }
}

// layer-1 nonlinearity + projection dot -> F table
__global__ void k_tail(const float* __restrict__ bhh1, const float* __restrict__ Wp,
                       const float* __restrict__ bp) {
    int i = blockIdx.x;
    float acc = 0.f;
    for (int ch = threadIdx.x; ch < HH; ch += 256) {
        float r = 1.f / (1.f + expf(-(g_gi[i][ch] + bhh1[ch])));
        float z = 1.f / (1.f + expf(-(g_gi[i][HH + ch] + bhh1[HH + ch])));
        float n = tanhf(g_gi[i][2 * HH + ch] + r * bhh1[2 * HH + ch]);
        acc += Wp[ch] * (1.f - z) * n;
    }
    __shared__ float sm[256];
    sm[threadIdx.x] = acc; __syncthreads();
    for (int st = 128; st > 0; st >>= 1) {
        if (threadIdx.x < st) sm[threadIdx.x] += sm[threadIdx.x + st];
        __syncthreads();
    }
    if (threadIdx.x == 0) g_Ftab[i] = sm[0] + bp[0];
}

// ---------------- sequential scan: 64 independent scalar recurrences ----------------
__global__ void k_scan(float* __restrict__ out) {
    __shared__ float tab[NF];
    int tid = threadIdx.x;  // 64
    for (int i = tid; i < NF; i += 64) tab[i] = g_Ftab[i];
    float R = domain_R();
    float invd = (float)(NF - 1) / (2.f * R);
    float k1 = 0.5f * invd;           // scales f and px
    float base = R * invd;            // -s0*invd
    __syncthreads();
    float* o = out + tid * TT;
    float f = 0.f;
    float buf[8];
#pragma unroll
    for (int i = 0; i < 8; i++) buf[i] = g_pxT[i][tid];
    for (int t0 = 0; t0 < TT; t0 += 8) {
#pragma unroll
        for (int i = 0; i < 8; i++) {
            float p = buf[i];
            int tn = t0 + 8 + i;
            if (tn < TT) buf[i] = g_pxT[tn][tid];   // prefetch: off the f-chain
            float pb = fmaf(p, k1, base);           // independent of f
            float u = fmaf(f, k1, pb);
            u = fminf(fmaxf(u, 1.0f), (float)(NF - 2) - 1e-3f);
            int idx = (int)u;                        // u >= 1 > 0: trunc == floor
            float xx = u - (float)idx;
            float p0 = tab[idx - 1], p1 = tab[idx], p2 = tab[idx + 1], p3 = tab[idx + 2];
            // 4-point Lagrange cubic on uniform grid
            float xm1 = xx - 1.f, xm2 = xx - 2.f, xp1 = xx + 1.f;
            float w0 = -xx * xm1 * xm2 * (1.f / 6.f);
            float w1 =  xp1 * xm1 * xm2 * 0.5f;
            float w2 = -xp1 * xx  * xm2 * 0.5f;
            float w3 =  xp1 * xx  * xm1 * (1.f / 6.f);
            f = fmaf(w0, p0, fmaf(w1, p1, fmaf(w2, p2, w3 * p3)));
            o[t0 + i] = f;
        }
    }
}

extern "C" void kernel_launch(void* const* d_in, const int* in_sizes, int n_in,
                              void* d_out, int out_size) {
    const float* x     = (const float*)d_in[0];
    // d_in[1] timestamp: unused
    const float* gamma = (const float*)d_in[2];
    const float* beta  = (const float*)d_in[3];
    const float* Wih0  = (const float*)d_in[4];
    const float* bih0  = (const float*)d_in[5];
    // d_in[6] W_hh0 unused (h_prev = 0)
    const float* bhh0  = (const float*)d_in[7];
    const float* Wih1  = (const float*)d_in[8];
    const float* bih1  = (const float*)d_in[9];
    // d_in[10] W_hh1 unused
    const float* bhh1  = (const float*)d_in[11];
    const float* Wp    = (const float*)d_in[12];
    const float* bp    = (const float*)d_in[13];
    float* out = (float*)d_out;

    k_stats<<<dim3(4, 64), 256>>>(x);
    k_finalize<<<1, 1024>>>(gamma, beta, Wp, bp);
    k_px<<<BT / 8, 256>>>(x);
    k_phi<<<dim3(NF, 4), 256>>>(Wih0, bih0, bhh0);
    k_gemm<<<dim3(48, NF / 64), 256>>>(Wih1, bih1);
    k_tail<<<NF, 256>>>(bhh1, Wp, bp);
    k_scan<<<1, 64>>>(out);
}